// round 1
// baseline (speedup 1.0000x reference)
#include <cuda_runtime.h>
#include <cuda_bf16.h>

#define BATCH 2
#define SEQ   2048
#define DIMSZ 1024
#define HEADS 16
#define DHEAD 64
#define INNER 1024
#define QKV3  3072
#define ROWS  (BATCH * SEQ)   // 4096

// ---------------- scratch (static device globals; no allocation) -------------
__device__ float g_xn[ROWS * DIMSZ];     // 16.8 MB
__device__ float g_qkv[ROWS * QKV3];     // 50.3 MB
__device__ float g_attn[ROWS * INNER];   // 16.8 MB

// ---------------- LayerNorm: one block per row -------------------------------
__global__ void __launch_bounds__(256) ln_kernel(
    const float* __restrict__ x, const float* __restrict__ gamma,
    const float* __restrict__ beta, float* __restrict__ out)
{
    int row = blockIdx.x;
    int t = threadIdx.x;
    const float4* xr = reinterpret_cast<const float4*>(x + (size_t)row * DIMSZ);
    float4 v = xr[t];
    float s  = v.x + v.y + v.z + v.w;
    float ss = v.x*v.x + v.y*v.y + v.z*v.z + v.w*v.w;
    #pragma unroll
    for (int o = 16; o; o >>= 1) {
        s  += __shfl_xor_sync(0xffffffffu, s,  o);
        ss += __shfl_xor_sync(0xffffffffu, ss, o);
    }
    __shared__ float sbuf[8], ssbuf[8];
    __shared__ float s_mu, s_rstd;
    int w = t >> 5, lane = t & 31;
    if (lane == 0) { sbuf[w] = s; ssbuf[w] = ss; }
    __syncthreads();
    if (t == 0) {
        float S = 0.f, SS = 0.f;
        #pragma unroll
        for (int i = 0; i < 8; i++) { S += sbuf[i]; SS += ssbuf[i]; }
        float mu = S * (1.0f / DIMSZ);
        float var = SS * (1.0f / DIMSZ) - mu * mu;
        s_mu = mu;
        s_rstd = rsqrtf(var + 1e-5f);
    }
    __syncthreads();
    float mu = s_mu, rstd = s_rstd;
    float4 g  = reinterpret_cast<const float4*>(gamma)[t];
    float4 bt = reinterpret_cast<const float4*>(beta)[t];
    float4 o4;
    o4.x = (v.x - mu) * rstd * g.x + bt.x;
    o4.y = (v.y - mu) * rstd * g.y + bt.y;
    o4.z = (v.z - mu) * rstd * g.z + bt.z;
    o4.w = (v.w - mu) * rstd * g.w + bt.w;
    reinterpret_cast<float4*>(out + (size_t)row * DIMSZ)[t] = o4;
}

// ---------------- fp32 SGEMM: C[M,Ntot] = A[M,K] @ B[K,Ntot] (+bias) ---------
// 128x128 tile, BK=8, 256 threads, 8x8 per thread.
__global__ void __launch_bounds__(256) sgemm_kernel(
    const float* __restrict__ A, const float* __restrict__ Bm,
    const float* __restrict__ bias, float* __restrict__ C,
    int M, int Ntot, int K)
{
    __shared__ float As[8 * 132];   // As[kk][r], padded
    __shared__ float Bs[8 * 128];   // Bs[kk][c]
    int tid = threadIdx.x;
    int tx = tid & 15, ty = tid >> 4;
    int c0 = blockIdx.x * 128;
    int r0 = blockIdx.y * 128;

    float acc[8][8];
    #pragma unroll
    for (int i = 0; i < 8; i++)
        #pragma unroll
        for (int j = 0; j < 8; j++) acc[i][j] = 0.f;

    int ar = tid >> 1;            // 0..127
    int ak = (tid & 1) * 4;       // 0 or 4
    int bk = tid >> 5;            // 0..7
    int bc = (tid & 31) * 4;      // 0..124

    const float* Aptr = A + (size_t)(r0 + ar) * K + ak;
    const float* Bptr = Bm + (size_t)bk * Ntot + c0 + bc;

    for (int k0 = 0; k0 < K; k0 += 8) {
        float4 a4 = *reinterpret_cast<const float4*>(Aptr + k0);
        float4 b4 = *reinterpret_cast<const float4*>(Bptr + (size_t)k0 * Ntot);
        As[(ak + 0) * 132 + ar] = a4.x;
        As[(ak + 1) * 132 + ar] = a4.y;
        As[(ak + 2) * 132 + ar] = a4.z;
        As[(ak + 3) * 132 + ar] = a4.w;
        *reinterpret_cast<float4*>(&Bs[bk * 128 + bc]) = b4;
        __syncthreads();
        #pragma unroll
        for (int kk = 0; kk < 8; kk++) {
            float a[8], b[8];
            *reinterpret_cast<float4*>(a)     = *reinterpret_cast<const float4*>(&As[kk * 132 + ty * 8]);
            *reinterpret_cast<float4*>(a + 4) = *reinterpret_cast<const float4*>(&As[kk * 132 + ty * 8 + 4]);
            *reinterpret_cast<float4*>(b)     = *reinterpret_cast<const float4*>(&Bs[kk * 128 + tx * 8]);
            *reinterpret_cast<float4*>(b + 4) = *reinterpret_cast<const float4*>(&Bs[kk * 128 + tx * 8 + 4]);
            #pragma unroll
            for (int i = 0; i < 8; i++)
                #pragma unroll
                for (int j = 0; j < 8; j++)
                    acc[i][j] += a[i] * b[j];
        }
        __syncthreads();
    }

    #pragma unroll
    for (int i = 0; i < 8; i++) {
        float* Crow = C + (size_t)(r0 + ty * 8 + i) * Ntot + c0 + tx * 8;
        #pragma unroll
        for (int j = 0; j < 8; j++) {
            float vv = acc[i][j];
            if (bias) vv += bias[c0 + tx * 8 + j];
            Crow[j] = vv;
        }
    }
}

// ---------------- flash attention (fp32, online softmax) ---------------------
// Block: 64 query rows for one (b, h). 256 threads (16x16), 4x4 outputs each.
// smem: Qs[d][r] pad65 | Ks[d][m] pad65 (reused as Ps[m][r]) | Vs[m][c] pad65
#define FA_SMEM (3 * 64 * 65 * 4)

__global__ void __launch_bounds__(256) flash_kernel(
    const float* __restrict__ qkv, float* __restrict__ out)
{
    int qt = blockIdx.x, h = blockIdx.y, b = blockIdx.z;
    extern __shared__ float sm[];
    float* Qs = sm;              // [64][65], Qs[d*65 + r]
    float* Ks = sm + 4160;       // [64][65], Ks[d*65 + m]; later Ps[m*65 + r]
    float* Vs = sm + 8320;       // [64][65], Vs[m*65 + c]

    int tid = threadIdx.x;
    int tx = tid & 15, ty = tid >> 4;
    int n0 = qt * 64;

    const float* qb = qkv + (size_t)b * SEQ * QKV3 + h * DHEAD;
    const float* kb = qb + INNER;
    const float* vb = qb + 2 * INNER;

    // load Q tile transposed
    for (int idx = tid; idx < 64 * 64; idx += 256) {
        int r = idx >> 6, d = idx & 63;
        Qs[d * 65 + r] = qb[(size_t)(n0 + r) * QKV3 + d];
    }

    float m_i[4], l_i[4], o[4][4];
    #pragma unroll
    for (int i = 0; i < 4; i++) {
        m_i[i] = -1e30f; l_i[i] = 0.f;
        #pragma unroll
        for (int j = 0; j < 4; j++) o[i][j] = 0.f;
    }

    const float scale = 0.125f;   // DHEAD^-0.5

    for (int kt = 0; kt < SEQ / 64; kt++) {
        __syncthreads();   // previous P@V reads done (also covers Q-load on kt=0)
        int m0 = kt * 64;
        for (int idx = tid; idx < 64 * 64; idx += 256) {
            int mrow = idx >> 6, d = idx & 63;
            float kv = kb[(size_t)(m0 + mrow) * QKV3 + d];
            float vv = vb[(size_t)(m0 + mrow) * QKV3 + d];
            Ks[d * 65 + mrow] = kv;
            Vs[mrow * 65 + d] = vv;
        }
        __syncthreads();

        // S = Q @ K^T
        float s[4][4];
        #pragma unroll
        for (int i = 0; i < 4; i++)
            #pragma unroll
            for (int j = 0; j < 4; j++) s[i][j] = 0.f;
        #pragma unroll 8
        for (int d = 0; d < 64; d++) {
            float a[4], bb[4];
            #pragma unroll
            for (int i = 0; i < 4; i++) a[i]  = Qs[d * 65 + ty * 4 + i];
            #pragma unroll
            for (int j = 0; j < 4; j++) bb[j] = Ks[d * 65 + tx * 4 + j];
            #pragma unroll
            for (int i = 0; i < 4; i++)
                #pragma unroll
                for (int j = 0; j < 4; j++)
                    s[i][j] += a[i] * bb[j];
        }

        // online softmax update (row groups = 16 lanes sharing ty)
        float p[4][4];
        #pragma unroll
        for (int i = 0; i < 4; i++) {
            float mloc = -1e30f;
            #pragma unroll
            for (int j = 0; j < 4; j++) mloc = fmaxf(mloc, s[i][j] * scale);
            #pragma unroll
            for (int off = 8; off; off >>= 1)
                mloc = fmaxf(mloc, __shfl_xor_sync(0xffffffffu, mloc, off));
            float mnew = fmaxf(m_i[i], mloc);
            float alpha = __expf(m_i[i] - mnew);
            float rsum = 0.f;
            #pragma unroll
            for (int j = 0; j < 4; j++) {
                p[i][j] = __expf(s[i][j] * scale - mnew);
                rsum += p[i][j];
            }
            #pragma unroll
            for (int off = 8; off; off >>= 1)
                rsum += __shfl_xor_sync(0xffffffffu, rsum, off);
            l_i[i] = l_i[i] * alpha + rsum;
            m_i[i] = mnew;
            #pragma unroll
            for (int j = 0; j < 4; j++) o[i][j] *= alpha;
        }

        __syncthreads();   // all S reads of Ks finished
        #pragma unroll
        for (int i = 0; i < 4; i++)
            #pragma unroll
            for (int j = 0; j < 4; j++)
                Ks[(tx * 4 + j) * 65 + (ty * 4 + i)] = p[i][j];  // Ps[m][r]
        __syncthreads();

        // O += P @ V
        #pragma unroll 8
        for (int mm = 0; mm < 64; mm++) {
            float a[4], bb[4];
            #pragma unroll
            for (int i = 0; i < 4; i++) a[i]  = Ks[mm * 65 + ty * 4 + i];
            #pragma unroll
            for (int j = 0; j < 4; j++) bb[j] = Vs[mm * 65 + tx * 4 + j];
            #pragma unroll
            for (int i = 0; i < 4; i++)
                #pragma unroll
                for (int j = 0; j < 4; j++)
                    o[i][j] += a[i] * bb[j];
        }
    }

    #pragma unroll
    for (int i = 0; i < 4; i++) {
        float inv = 1.0f / l_i[i];
        float* orow = out + (size_t)(b * SEQ + n0 + ty * 4 + i) * INNER
                          + h * DHEAD + tx * 4;
        #pragma unroll
        for (int j = 0; j < 4; j++) orow[j] = o[i][j] * inv;
    }
}

// ---------------- launcher ---------------------------------------------------
extern "C" void kernel_launch(void* const* d_in, const int* in_sizes, int n_in,
                              void* d_out, int out_size)
{
    const float* x     = (const float*)d_in[0];
    const float* gamma = (const float*)d_in[1];
    const float* beta  = (const float*)d_in[2];
    const float* Wqkv  = (const float*)d_in[3];
    const float* Wout  = (const float*)d_in[4];
    const float* bout  = (const float*)d_in[5];
    float* out = (float*)d_out;

    float *xn, *qkvbuf, *attnbuf;
    cudaGetSymbolAddress((void**)&xn,      g_xn);
    cudaGetSymbolAddress((void**)&qkvbuf,  g_qkv);
    cudaGetSymbolAddress((void**)&attnbuf, g_attn);

    cudaFuncSetAttribute(flash_kernel,
                         cudaFuncAttributeMaxDynamicSharedMemorySize, FA_SMEM);

    // 1) LayerNorm
    ln_kernel<<<ROWS, 256>>>(x, gamma, beta, xn);

    // 2) QKV projection: [4096,1024] @ [1024,3072]
    sgemm_kernel<<<dim3(QKV3 / 128, ROWS / 128), 256>>>(
        xn, Wqkv, nullptr, qkvbuf, ROWS, QKV3, DIMSZ);

    // 3) attention
    flash_kernel<<<dim3(SEQ / 64, HEADS, BATCH), 256, FA_SMEM>>>(qkvbuf, attnbuf);

    // 4) output projection + bias: [4096,1024] @ [1024,1024]
    sgemm_kernel<<<dim3(DIMSZ / 128, ROWS / 128), 256>>>(
        attnbuf, Wout, bout, out, ROWS, DIMSZ, DIMSZ);
}

// round 4
// speedup vs baseline: 2.8511x; 2.8511x over previous
#include <cuda_runtime.h>
#include <cuda_bf16.h>
#include <cuda_fp16.h>
#include <cstdint>

#define BATCH 2
#define SEQ   2048
#define DIMSZ 1024
#define HEADS 16
#define DHEAD 64
#define INNER 1024
#define QKV3  3072
#define ROWS  (BATCH * SEQ)   // 4096

// ---------------- scratch (static device globals; no allocation) -------------
__device__ float g_qkv[ROWS * QKV3];              // 50.3 MB fp32
__device__ __nv_bfloat16 g_xnh[ROWS * DIMSZ];
__device__ __nv_bfloat16 g_xnl[ROWS * DIMSZ];
__device__ __nv_bfloat16 g_wqh[QKV3 * DIMSZ];     // Wqkv^T [3072][1024]
__device__ __nv_bfloat16 g_wql[QKV3 * DIMSZ];
__device__ __nv_bfloat16 g_woh[DIMSZ * INNER];    // Wout^T [1024][1024]
__device__ __nv_bfloat16 g_wol[DIMSZ * INNER];
__device__ __nv_bfloat16 g_aoh[ROWS * INNER];
__device__ __nv_bfloat16 g_aol[ROWS * INNER];

// ---------------- helpers ----------------------------------------------------
__device__ __forceinline__ uint32_t smem_u32(const void* p) {
    uint32_t a;
    asm("{ .reg .u64 t; cvta.to.shared.u64 t, %1; cvt.u32.u64 %0, t; }"
        : "=r"(a) : "l"(p));
    return a;
}
__device__ __forceinline__ void cp16(uint32_t dst, const void* src) {
    asm volatile("cp.async.cg.shared.global [%0], [%1], 16;"
                 :: "r"(dst), "l"(src) : "memory");
}
__device__ __forceinline__ void ldm4(uint32_t* r, uint32_t addr) {
    asm volatile("ldmatrix.sync.aligned.m8n8.x4.shared.b16 {%0,%1,%2,%3}, [%4];"
        : "=r"(r[0]), "=r"(r[1]), "=r"(r[2]), "=r"(r[3]) : "r"(addr));
}
__device__ __forceinline__ void ldm4t(uint32_t* r, uint32_t addr) {
    asm volatile("ldmatrix.sync.aligned.m8n8.x4.trans.shared.b16 {%0,%1,%2,%3}, [%4];"
        : "=r"(r[0]), "=r"(r[1]), "=r"(r[2]), "=r"(r[3]) : "r"(addr));
}
__device__ __forceinline__ void mma_bf16(float* d, const uint32_t* a,
                                         uint32_t b0, uint32_t b1) {
    asm volatile("mma.sync.aligned.m16n8k16.row.col.f32.bf16.bf16.f32 "
        "{%0,%1,%2,%3}, {%4,%5,%6,%7}, {%8,%9}, {%0,%1,%2,%3};"
        : "+f"(d[0]), "+f"(d[1]), "+f"(d[2]), "+f"(d[3])
        : "r"(a[0]), "r"(a[1]), "r"(a[2]), "r"(a[3]), "r"(b0), "r"(b1));
}
__device__ __forceinline__ void mma_f16(float* d, const uint32_t* a,
                                        uint32_t b0, uint32_t b1) {
    asm volatile("mma.sync.aligned.m16n8k16.row.col.f32.f16.f16.f32 "
        "{%0,%1,%2,%3}, {%4,%5,%6,%7}, {%8,%9}, {%0,%1,%2,%3};"
        : "+f"(d[0]), "+f"(d[1]), "+f"(d[2]), "+f"(d[3])
        : "r"(a[0]), "r"(a[1]), "r"(a[2]), "r"(a[3]), "r"(b0), "r"(b1));
}
__device__ __forceinline__ void mma_tf32(float* d, const uint32_t* a,
                                         uint32_t b0, uint32_t b1) {
    asm volatile("mma.sync.aligned.m16n8k8.row.col.f32.tf32.tf32.f32 "
        "{%0,%1,%2,%3}, {%4,%5,%6,%7}, {%8,%9}, {%0,%1,%2,%3};"
        : "+f"(d[0]), "+f"(d[1]), "+f"(d[2]), "+f"(d[3])
        : "r"(a[0]), "r"(a[1]), "r"(a[2]), "r"(a[3]), "r"(b0), "r"(b1));
}
__device__ __forceinline__ uint32_t to_tf32(float f) {
    uint32_t r; asm("cvt.rna.tf32.f32 %0, %1;" : "=r"(r) : "f"(f)); return r;
}
__device__ __forceinline__ uint32_t h2u(float a, float b) {
    __half2 h = __floats2half2_rn(a, b);
    return *reinterpret_cast<uint32_t*>(&h);
}
__device__ __forceinline__ void split_bf16(float v, __nv_bfloat16& h, __nv_bfloat16& l) {
    h = __float2bfloat16(v);
    l = __float2bfloat16(v - __bfloat162float(h));
}

// ---------------- LayerNorm -> split bf16 ------------------------------------
__global__ void __launch_bounds__(256) ln_split_kernel(
    const float* __restrict__ x, const float* __restrict__ gamma,
    const float* __restrict__ beta,
    __nv_bfloat16* __restrict__ oh, __nv_bfloat16* __restrict__ ol)
{
    int row = blockIdx.x;
    int t = threadIdx.x;
    const float4* xr = reinterpret_cast<const float4*>(x + (size_t)row * DIMSZ);
    float4 v = xr[t];
    float s  = v.x + v.y + v.z + v.w;
    float ss = v.x*v.x + v.y*v.y + v.z*v.z + v.w*v.w;
    #pragma unroll
    for (int o = 16; o; o >>= 1) {
        s  += __shfl_xor_sync(0xffffffffu, s,  o);
        ss += __shfl_xor_sync(0xffffffffu, ss, o);
    }
    __shared__ float sbuf[8], ssbuf[8];
    __shared__ float s_mu, s_rstd;
    int w = t >> 5, lane = t & 31;
    if (lane == 0) { sbuf[w] = s; ssbuf[w] = ss; }
    __syncthreads();
    if (t == 0) {
        float S = 0.f, SS = 0.f;
        #pragma unroll
        for (int i = 0; i < 8; i++) { S += sbuf[i]; SS += ssbuf[i]; }
        float mu = S * (1.0f / DIMSZ);
        float var = SS * (1.0f / DIMSZ) - mu * mu;
        s_mu = mu; s_rstd = rsqrtf(var + 1e-5f);
    }
    __syncthreads();
    float mu = s_mu, rstd = s_rstd;
    float4 g  = reinterpret_cast<const float4*>(gamma)[t];
    float4 bt = reinterpret_cast<const float4*>(beta)[t];
    float o0 = (v.x - mu) * rstd * g.x + bt.x;
    float o1 = (v.y - mu) * rstd * g.y + bt.y;
    float o2 = (v.z - mu) * rstd * g.z + bt.z;
    float o3 = (v.w - mu) * rstd * g.w + bt.w;
    __nv_bfloat16 h0,h1,h2,h3,l0,l1,l2,l3;
    split_bf16(o0,h0,l0); split_bf16(o1,h1,l1);
    split_bf16(o2,h2,l2); split_bf16(o3,h3,l3);
    size_t base = (size_t)row * DIMSZ + t * 4;
    __nv_bfloat162* oh2 = reinterpret_cast<__nv_bfloat162*>(oh + base);
    __nv_bfloat162* ol2 = reinterpret_cast<__nv_bfloat162*>(ol + base);
    oh2[0] = __nv_bfloat162(h0,h1); oh2[1] = __nv_bfloat162(h2,h3);
    ol2[0] = __nv_bfloat162(l0,l1); ol2[1] = __nv_bfloat162(l2,l3);
}

// ------------- weight transpose + split: in [K][N] fp32 -> out [N][K] bf16 ---
__global__ void __launch_bounds__(256) transpose_split_kernel(
    const float* __restrict__ in, __nv_bfloat16* __restrict__ oh,
    __nv_bfloat16* __restrict__ ol, int K, int N)
{
    __shared__ float t[32][33];
    int n0 = blockIdx.x * 32, k0 = blockIdx.y * 32;
    int tx = threadIdx.x, ty = threadIdx.y;  // 32 x 8
    #pragma unroll
    for (int i = 0; i < 4; i++)
        t[ty + i*8][tx] = in[(size_t)(k0 + ty + i*8) * N + n0 + tx];
    __syncthreads();
    #pragma unroll
    for (int i = 0; i < 4; i++) {
        float v = t[tx][ty + i*8];
        __nv_bfloat16 h, l;
        split_bf16(v, h, l);
        size_t o = (size_t)(n0 + ty + i*8) * K + k0 + tx;
        oh[o] = h; ol[o] = l;
    }
}

// ---------------- warp-mma split-bf16 GEMM -----------------------------------
// C[M,Ntot] = A[M,1024] @ B[Ntot,1024]^T, K=1024, split hi/lo, 3 MMAs.
// CTA 128x128, BK=32, 8 warps (2m x 4n), warp tile 64x32. cp.async double buf.
#define GS_ARR   10240                 // 128 rows * 80B
#define GS_STAGE (4 * GS_ARR)          // Ah,Al,Bh,Bl
#define GS_SMEM  (2 * GS_STAGE)        // 81920

__global__ void __launch_bounds__(256, 1) wm_gemm_kernel(
    const __nv_bfloat16* __restrict__ Ah, const __nv_bfloat16* __restrict__ Al,
    const __nv_bfloat16* __restrict__ Bh, const __nv_bfloat16* __restrict__ Bl,
    const float* __restrict__ bias, float* __restrict__ C, int Ntot)
{
    extern __shared__ char sm[];
    const int tid = threadIdx.x, lane = tid & 31, wid = tid >> 5;
    const int wm = wid >> 2, wn = wid & 3;
    const int c0 = blockIdx.x * 128, r0 = blockIdx.y * 128;
    uint32_t sbase = smem_u32(sm);

    auto issue = [&](int c, int st) {
        int k0 = c * 32;
        #pragma unroll
        for (int i = 0; i < 8; i++) {
            int q = tid + i * 256;
            int arr = q >> 9, rem = q & 511, row = rem >> 2, kc = rem & 3;
            const __nv_bfloat16* s;
            if (arr == 0)      s = Ah + (size_t)(r0 + row) * 1024 + k0 + kc * 8;
            else if (arr == 1) s = Al + (size_t)(r0 + row) * 1024 + k0 + kc * 8;
            else if (arr == 2) s = Bh + (size_t)(c0 + row) * 1024 + k0 + kc * 8;
            else               s = Bl + (size_t)(c0 + row) * 1024 + k0 + kc * 8;
            cp16(sbase + st * GS_STAGE + arr * GS_ARR + row * 80 + kc * 16, s);
        }
        asm volatile("cp.async.commit_group;" ::: "memory");
    };

    float acc[4][4][4];
    #pragma unroll
    for (int a = 0; a < 4; a++)
        #pragma unroll
        for (int b = 0; b < 4; b++)
            #pragma unroll
            for (int cc = 0; cc < 4; cc++) acc[a][b][cc] = 0.f;

    issue(0, 0);

    const int mat  = lane >> 3;
    const int roff = (mat & 1) * 8 + (lane & 7);
    const int cofs = (mat >> 1) * 16;

    for (int c = 0; c < 32; c++) {
        if (c + 1 < 32) {
            issue(c + 1, (c + 1) & 1);
            asm volatile("cp.async.wait_group 1;" ::: "memory");
        } else {
            asm volatile("cp.async.wait_group 0;" ::: "memory");
        }
        __syncthreads();
        uint32_t base = sbase + (c & 1) * GS_STAGE;
        #pragma unroll
        for (int ks = 0; ks < 2; ks++) {
            uint32_t ah[4][4], alr[4][4], bh[2][4], blr[2][4];
            #pragma unroll
            for (int mt = 0; mt < 4; mt++) {
                uint32_t ad = base + (wm*64 + mt*16 + roff) * 80 + ks*32 + cofs;
                ldm4(ah[mt], ad);
                ldm4(alr[mt], ad + GS_ARR);
            }
            #pragma unroll
            for (int nt2 = 0; nt2 < 2; nt2++) {
                uint32_t bd = base + 2*GS_ARR + (wn*32 + nt2*16 + roff) * 80 + ks*32 + cofs;
                ldm4(bh[nt2], bd);
                ldm4(blr[nt2], bd + GS_ARR);
            }
            #pragma unroll
            for (int mt = 0; mt < 4; mt++)
                #pragma unroll
                for (int nt = 0; nt < 4; nt++) {
                    int n2 = nt >> 1, hf = nt & 1;
                    mma_bf16(acc[mt][nt], ah[mt],  bh[n2][hf],  bh[n2][2+hf]);
                    mma_bf16(acc[mt][nt], alr[mt], bh[n2][hf],  bh[n2][2+hf]);
                    mma_bf16(acc[mt][nt], ah[mt],  blr[n2][hf], blr[n2][2+hf]);
                }
        }
        __syncthreads();
    }

    #pragma unroll
    for (int mt = 0; mt < 4; mt++) {
        int rbase = r0 + wm*64 + mt*16 + (lane >> 2);
        #pragma unroll
        for (int nt = 0; nt < 4; nt++) {
            int col = c0 + wn*32 + nt*8 + 2*(lane & 3);
            float b0v = bias ? bias[col] : 0.f;
            float b1v = bias ? bias[col + 1] : 0.f;
            float2 v0 = {acc[mt][nt][0] + b0v, acc[mt][nt][1] + b1v};
            float2 v1 = {acc[mt][nt][2] + b0v, acc[mt][nt][3] + b1v};
            *reinterpret_cast<float2*>(C + (size_t)rbase * Ntot + col) = v0;
            *reinterpret_cast<float2*>(C + (size_t)(rbase + 8) * Ntot + col) = v1;
        }
    }
}

// ---------------- flash attention: tf32 QK + fp16 PV -------------------------
// CTA: 128 q rows (8 warps x m16), kv-tile 64. Q prescaled by 0.125.
#define FA2_SMEM 34816   // max(Q 128*68*4, K 64*68*4 + V 64*128)

__global__ void __launch_bounds__(256, 1) fa_kernel(
    const float* __restrict__ qkv,
    __nv_bfloat16* __restrict__ outh, __nv_bfloat16* __restrict__ outl)
{
    extern __shared__ char sm[];
    uint32_t* Ks = reinterpret_cast<uint32_t*>(sm);       // [64][68] tf32
    char* Vs = sm + 64 * 68 * 4;                          // [64][128B] swizzled fp16
    uint32_t* Qs = reinterpret_cast<uint32_t*>(sm);       // [128][68] (init only)

    const int tid = threadIdx.x, lane = tid & 31, wid = tid >> 5;
    const int qt = blockIdx.x, hd = blockIdx.y, b = blockIdx.z;
    const int n0 = qt * 128;
    const int lr = lane >> 2, lc = lane & 3;

    const float* qb = qkv + (size_t)b * SEQ * QKV3 + hd * DHEAD;
    const float* kb = qb + 1024;
    const float* vb = qb + 2048;

    // stage Q (prescaled, tf32)
    #pragma unroll
    for (int i = 0; i < 8; i++) {
        int q = tid + i * 256;        // 2048 float4 chunks = 128 rows * 16
        int row = q >> 4, c4 = (q & 15) * 4;
        float4 v = *reinterpret_cast<const float4*>(qb + (size_t)(n0 + row) * QKV3 + c4);
        uint4 t;
        t.x = to_tf32(v.x * 0.125f); t.y = to_tf32(v.y * 0.125f);
        t.z = to_tf32(v.z * 0.125f); t.w = to_tf32(v.w * 0.125f);
        *reinterpret_cast<uint4*>(&Qs[row * 68 + c4]) = t;
    }
    __syncthreads();

    uint32_t qa[8][4];
    {
        int m0 = wid * 16;
        #pragma unroll
        for (int u = 0; u < 8; u++) {
            qa[u][0] = Qs[(m0 + lr)     * 68 + u*8 + lc];
            qa[u][1] = Qs[(m0 + 8 + lr) * 68 + u*8 + lc];
            qa[u][2] = Qs[(m0 + lr)     * 68 + u*8 + 4 + lc];
            qa[u][3] = Qs[(m0 + 8 + lr) * 68 + u*8 + 4 + lc];
        }
    }
    __syncthreads();

    float m_i[2] = {-1e30f, -1e30f}, l_i[2] = {0.f, 0.f};
    float o[8][4];
    #pragma unroll
    for (int v = 0; v < 8; v++)
        #pragma unroll
        for (int j = 0; j < 4; j++) o[v][j] = 0.f;

    const uint32_t vsb = smem_u32(Vs);

    for (int kt = 0; kt < SEQ / 64; kt++) {
        int s0 = kt * 64;
        #pragma unroll
        for (int i = 0; i < 4; i++) {
            int q = tid + i * 256;    // 1024 float4 chunks = 64 rows * 16
            int row = q >> 4, c4 = (q & 15) * 4;
            float4 kv = *reinterpret_cast<const float4*>(kb + (size_t)(s0 + row) * QKV3 + c4);
            uint4 t = {to_tf32(kv.x), to_tf32(kv.y), to_tf32(kv.z), to_tf32(kv.w)};
            *reinterpret_cast<uint4*>(&Ks[row * 68 + c4]) = t;
            float4 vv = *reinterpret_cast<const float4*>(vb + (size_t)(s0 + row) * QKV3 + c4);
            uint2 hp = {h2u(vv.x, vv.y), h2u(vv.z, vv.w)};
            uint32_t off = row * 128 + c4 * 2;
            off ^= ((off >> 7) & 7) << 4;
            *reinterpret_cast<uint2*>(Vs + off) = hp;
        }
        __syncthreads();

        // S = Q K^T  (tf32)
        float s[8][4];
        #pragma unroll
        for (int v = 0; v < 8; v++)
            #pragma unroll
            for (int j = 0; j < 4; j++) s[v][j] = 0.f;
        #pragma unroll
        for (int u = 0; u < 8; u++) {
            #pragma unroll
            for (int v = 0; v < 8; v++) {
                uint32_t kb0 = Ks[(v*8 + lr) * 68 + u*8 + lc];
                uint32_t kb1 = Ks[(v*8 + lr) * 68 + u*8 + 4 + lc];
                mma_tf32(s[v], qa[u], kb0, kb1);
            }
        }

        // online softmax (rows: lr and lr+8)
        #pragma unroll
        for (int h = 0; h < 2; h++) {
            float mx = -1e30f;
            #pragma unroll
            for (int v = 0; v < 8; v++)
                mx = fmaxf(mx, fmaxf(s[v][2*h], s[v][2*h+1]));
            mx = fmaxf(mx, __shfl_xor_sync(0xffffffffu, mx, 1));
            mx = fmaxf(mx, __shfl_xor_sync(0xffffffffu, mx, 2));
            float mnew = fmaxf(m_i[h], mx);
            float alpha = __expf(m_i[h] - mnew);
            m_i[h] = mnew;
            float rs = 0.f;
            #pragma unroll
            for (int v = 0; v < 8; v++) {
                s[v][2*h]   = __expf(s[v][2*h]   - mnew);
                s[v][2*h+1] = __expf(s[v][2*h+1] - mnew);
                rs += s[v][2*h] + s[v][2*h+1];
            }
            rs += __shfl_xor_sync(0xffffffffu, rs, 1);
            rs += __shfl_xor_sync(0xffffffffu, rs, 2);
            l_i[h] = l_i[h] * alpha + rs;
            #pragma unroll
            for (int v = 0; v < 8; v++) {
                o[v][2*h]   *= alpha;
                o[v][2*h+1] *= alpha;
            }
        }

        // pack P to fp16 A-fragments (k16 tiles over the 64 kv positions)
        uint32_t pa[4][4];
        #pragma unroll
        for (int u = 0; u < 4; u++) {
            pa[u][0] = h2u(s[2*u][0],   s[2*u][1]);
            pa[u][1] = h2u(s[2*u][2],   s[2*u][3]);
            pa[u][2] = h2u(s[2*u+1][0], s[2*u+1][1]);
            pa[u][3] = h2u(s[2*u+1][2], s[2*u+1][3]);
        }

        // O += P V  (fp16 MMA, fp32 accum)
        #pragma unroll
        for (int u = 0; u < 4; u++) {
            #pragma unroll
            for (int w2 = 0; w2 < 4; w2++) {
                int mt = lane >> 3;
                int row = u*16 + (mt & 1) * 8 + (lane & 7);
                int colb = w2*32 + (mt >> 1) * 16;
                uint32_t off = (uint32_t)(row * 128 + colb);
                off ^= ((off >> 7) & 7) << 4;
                uint32_t r[4];
                ldm4t(r, vsb + off);
                mma_f16(o[2*w2],     pa[u], r[0], r[1]);
                mma_f16(o[2*w2 + 1], pa[u], r[2], r[3]);
            }
        }
        __syncthreads();
    }

    // epilogue: normalize + split-bf16 store
    #pragma unroll
    for (int h = 0; h < 2; h++) {
        float inv = 1.f / l_i[h];
        int rowg = b * SEQ + n0 + wid*16 + h*8 + lr;
        #pragma unroll
        for (int v = 0; v < 8; v++) {
            int col = hd * 64 + v*8 + 2*lc;
            float f0 = o[v][2*h]   * inv;
            float f1 = o[v][2*h+1] * inv;
            __nv_bfloat16 h0, l0, h1, l1;
            split_bf16(f0, h0, l0);
            split_bf16(f1, h1, l1);
            *reinterpret_cast<__nv_bfloat162*>(outh + (size_t)rowg * INNER + col) =
                __nv_bfloat162(h0, h1);
            *reinterpret_cast<__nv_bfloat162*>(outl + (size_t)rowg * INNER + col) =
                __nv_bfloat162(l0, l1);
        }
    }
}

// ---------------- launcher ---------------------------------------------------
extern "C" void kernel_launch(void* const* d_in, const int* in_sizes, int n_in,
                              void* d_out, int out_size)
{
    const float* x     = (const float*)d_in[0];
    const float* gamma = (const float*)d_in[1];
    const float* beta  = (const float*)d_in[2];
    const float* Wqkv  = (const float*)d_in[3];
    const float* Wout  = (const float*)d_in[4];
    const float* bout  = (const float*)d_in[5];
    float* out = (float*)d_out;

    float* qkvbuf;
    __nv_bfloat16 *xnh, *xnl, *wqh, *wql, *woh, *wol, *aoh, *aol;
    cudaGetSymbolAddress((void**)&qkvbuf, g_qkv);
    cudaGetSymbolAddress((void**)&xnh, g_xnh);
    cudaGetSymbolAddress((void**)&xnl, g_xnl);
    cudaGetSymbolAddress((void**)&wqh, g_wqh);
    cudaGetSymbolAddress((void**)&wql, g_wql);
    cudaGetSymbolAddress((void**)&woh, g_woh);
    cudaGetSymbolAddress((void**)&wol, g_wol);
    cudaGetSymbolAddress((void**)&aoh, g_aoh);
    cudaGetSymbolAddress((void**)&aol, g_aol);

    cudaFuncSetAttribute(wm_gemm_kernel,
                         cudaFuncAttributeMaxDynamicSharedMemorySize, GS_SMEM);

    ln_split_kernel<<<ROWS, 256>>>(x, gamma, beta, xnh, xnl);

    transpose_split_kernel<<<dim3(QKV3 / 32, DIMSZ / 32), dim3(32, 8)>>>(
        Wqkv, wqh, wql, DIMSZ, QKV3);
    transpose_split_kernel<<<dim3(DIMSZ / 32, DIMSZ / 32), dim3(32, 8)>>>(
        Wout, woh, wol, INNER, DIMSZ);

    wm_gemm_kernel<<<dim3(QKV3 / 128, ROWS / 128), 256, GS_SMEM>>>(
        xnh, xnl, wqh, wql, nullptr, qkvbuf, QKV3);

    fa_kernel<<<dim3(SEQ / 128, HEADS, BATCH), 256, FA2_SMEM>>>(qkvbuf, aoh, aol);

    wm_gemm_kernel<<<dim3(DIMSZ / 128, ROWS / 128), 256, GS_SMEM>>>(
        aoh, aol, woh, wol, bout, out, DIMSZ);
}